// round 3
// baseline (speedup 1.0000x reference)
#include <cuda_runtime.h>
#include <math.h>

// Problem constants (fixed shapes for this problem)
#define NN    20000
#define EE    640000
#define ETOT0 (EE + NN)
#define TXT   768
#define MELK  6400
#define HID   128

// ---------------- scratch (static device globals; no allocation) -------------
__device__ float g_melf[NN * HID];     // relu(mel @ mel_W + b)
__device__ float g_x0  [NN * HID];     // elu(concat @ concat_W + b)
__device__ float g_h1  [NN * 256];     // x0 @ g1_W
__device__ float g_x1  [NN * 256];     // GAT1 output (after elu)
__device__ float g_as1 [NN * 2];
__device__ float g_ad1 [NN * 2];
__device__ float g_h2  [NN * 4];
__device__ float g_as2 [NN];
__device__ float g_ad2 [NN];
__device__ int   g_deg [NN];
__device__ int   g_rowptr[NN + 1];
__device__ int   g_cursor[NN];
__device__ int   g_csr[ETOT0];

__device__ __forceinline__ float eluf(float x) { return x > 0.f ? x : expm1f(x); }
__device__ __forceinline__ float lrelu(float x) { return x > 0.f ? x : 0.2f * x; }

// ---------------- GEMM: C[M,Nout] = act(A[M,K] @ W[K,Nout] + bias) -----------
// A is a logical concat of A1 (cols [0,ksplit)) and A2 (cols [ksplit,K)).
// BM=64, BN=128, BK=16, 256 threads, 4x8 microtile per thread.
#define BM 64
#define BN 128
#define BK 16

__global__ __launch_bounds__(256) void gemm_kernel(
    const float* __restrict__ A1, int lda1, int ksplit,
    const float* __restrict__ A2, int lda2,
    const float* __restrict__ W, int ldw,
    const float* __restrict__ bias,
    float* __restrict__ C, int ldc,
    int M, int K, int act)
{
    __shared__ float As[BK][BM];
    __shared__ float Bs[BK][BN];
    const int tid    = threadIdx.x;
    const int brow   = blockIdx.x * BM;
    const int colOff = blockIdx.y * BN;
    const int tr = tid >> 4;      // 0..15 -> rows tr*4..tr*4+3
    const int tc = tid & 15;      // 0..15 -> cols tc*8..tc*8+7

    float acc[4][8];
#pragma unroll
    for (int i = 0; i < 4; i++)
#pragma unroll
        for (int j = 0; j < 8; j++) acc[i][j] = 0.f;

    const int ar  = tid >> 2;          // 0..63
    const int ac4 = (tid & 3) * 4;     // 0,4,8,12
    const int bkr = tid >> 4;          // 0..15
    const int bc  = (tid & 15) * 8;    // 0..120

    for (int k0 = 0; k0 < K; k0 += BK) {
        // load A tile (64x16) as one float4 per thread, transposed into As[k][m]
        {
            const int gr = brow + ar;
            float4 v = make_float4(0.f, 0.f, 0.f, 0.f);
            if (gr < M) {
                const int k = k0 + ac4;   // ksplit is a multiple of 16 -> no straddle
                const float* p = (k < ksplit)
                    ? (A1 + (size_t)gr * lda1 + k)
                    : (A2 + (size_t)gr * lda2 + (k - ksplit));
                v = *(const float4*)p;
            }
            As[ac4 + 0][ar] = v.x;
            As[ac4 + 1][ar] = v.y;
            As[ac4 + 2][ar] = v.z;
            As[ac4 + 3][ar] = v.w;
        }
        // load B tile (16x128) as two float4 per thread
        {
            const float* p = W + (size_t)(k0 + bkr) * ldw + colOff + bc;
            float4 v0 = *(const float4*)p;
            float4 v1 = *(const float4*)(p + 4);
            *(float4*)&Bs[bkr][bc]     = v0;
            *(float4*)&Bs[bkr][bc + 4] = v1;
        }
        __syncthreads();
#pragma unroll
        for (int kk = 0; kk < BK; kk++) {
            float a[4], b[8];
            *(float4*)a       = *(const float4*)&As[kk][tr * 4];
            *(float4*)b       = *(const float4*)&Bs[kk][tc * 8];
            *(float4*)(b + 4) = *(const float4*)&Bs[kk][tc * 8 + 4];
#pragma unroll
            for (int i = 0; i < 4; i++)
#pragma unroll
                for (int j = 0; j < 8; j++)
                    acc[i][j] = fmaf(a[i], b[j], acc[i][j]);
        }
        __syncthreads();
    }

#pragma unroll
    for (int i = 0; i < 4; i++) {
        const int gr = brow + tr * 4 + i;
        if (gr >= M) continue;
#pragma unroll
        for (int j = 0; j < 8; j++) {
            const int col = colOff + tc * 8 + j;
            float v = acc[i][j];
            if (bias) v += bias[col];
            if (act == 1)      v = fmaxf(v, 0.f);
            else if (act == 2) v = eluf(v);
            C[(size_t)gr * ldc + col] = v;
        }
    }
}

// ---------------- CSR build ---------------------------------------------------
__global__ void init_deg_kernel(int n)
{
    int i = blockIdx.x * blockDim.x + threadIdx.x;
    if (i < n) g_deg[i] = 0;
}

__global__ void hist_kernel(const int* __restrict__ ei, int E, int Etot)
{
    int e = blockIdx.x * blockDim.x + threadIdx.x;
    if (e >= Etot) return;
    int dst = (e < E) ? ei[E + e] : (e - E);   // self loops appended
    atomicAdd(&g_deg[dst], 1);
}

// single-block exclusive scan of g_deg -> g_rowptr / g_cursor
__global__ __launch_bounds__(1024) void scan_kernel(int n)
{
    __shared__ int sb[1024];
    const int tid = threadIdx.x;
    const int CH  = (NN + 1023) / 1024;   // 20
    int local[CH];
    int base = tid * CH;
    int sum = 0;
#pragma unroll
    for (int j = 0; j < CH; j++) {
        int idx = base + j;
        int v = (idx < n) ? g_deg[idx] : 0;
        local[j] = v;
        sum += v;
    }
    sb[tid] = sum;
    __syncthreads();
    for (int off = 1; off < 1024; off <<= 1) {
        int v = (tid >= off) ? sb[tid - off] : 0;
        __syncthreads();
        sb[tid] += v;
        __syncthreads();
    }
    int run = sb[tid] - sum;   // exclusive prefix for this chunk
#pragma unroll
    for (int j = 0; j < CH; j++) {
        int idx = base + j;
        if (idx < n) {
            g_rowptr[idx] = run;
            g_cursor[idx] = run;
            run += local[j];
        }
    }
    if (tid == 1023) g_rowptr[n] = sb[1023];
}

__global__ void scatter_kernel(const int* __restrict__ ei, int E, int Etot)
{
    int e = blockIdx.x * blockDim.x + threadIdx.x;
    if (e >= Etot) return;
    int src, dst;
    if (e < E) { src = ei[e]; dst = ei[E + e]; }
    else       { src = e - E; dst = e - E; }
    int pos = atomicAdd(&g_cursor[dst], 1);
    g_csr[pos] = src;
}

// ---------------- GAT1 attention coefficients ---------------------------------
// as1[n,h] = <h1[n,h,:], g1_as[h,:]>, ad1 likewise. One warp per (n,h).
__global__ __launch_bounds__(256) void att1_kernel(
    const float* __restrict__ g1_as, const float* __restrict__ g1_ad, int n)
{
    int p = blockIdx.x * 8 + (threadIdx.x >> 5);
    int lane = threadIdx.x & 31;
    if (p >= n * 2) return;
    int node = p >> 1, h = p & 1;
    float4 hv = *(const float4*)(g_h1 + (size_t)node * 256 + h * 128 + lane * 4);
    float4 as = *(const float4*)(g1_as + h * 128 + lane * 4);
    float4 ad = *(const float4*)(g1_ad + h * 128 + lane * 4);
    float vs = hv.x * as.x + hv.y * as.y + hv.z * as.z + hv.w * as.w;
    float vd = hv.x * ad.x + hv.y * ad.y + hv.z * ad.z + hv.w * ad.w;
#pragma unroll
    for (int o = 16; o; o >>= 1) {
        vs += __shfl_xor_sync(0xffffffffu, vs, o);
        vd += __shfl_xor_sync(0xffffffffu, vd, o);
    }
    if (lane == 0) { g_as1[p] = vs; g_ad1[p] = vd; }
}

// ---------------- GAT1 aggregate (atomic-free via CSR) ------------------------
// One warp per (node, head). Pass 1: segment max. Pass 2: exp-weighted sum of
// h1[src,head,:] (warp cooperatively loads 128 floats = 4/lane per edge).
__global__ __launch_bounds__(256) void gat1_kernel(const float* __restrict__ g1_b, int n)
{
    int p = blockIdx.x * 8 + (threadIdx.x >> 5);
    int lane = threadIdx.x & 31;
    if (p >= n * 2) return;
    int node = p >> 1, h = p & 1;
    int beg = g_rowptr[node], end = g_rowptr[node + 1];
    float adv = g_ad1[node * 2 + h];

    float m = -1e30f;
    for (int i = beg + lane; i < end; i += 32) {
        int s = g_csr[i];
        m = fmaxf(m, lrelu(g_as1[s * 2 + h] + adv));
    }
#pragma unroll
    for (int o = 16; o; o >>= 1) m = fmaxf(m, __shfl_xor_sync(0xffffffffu, m, o));

    float ssum = 0.f, ax = 0.f, ay = 0.f, az = 0.f, aw = 0.f;
    const float* hb = g_h1 + h * 128 + lane * 4;
    for (int i = beg; i < end; ++i) {
        int s = g_csr[i];                                // broadcast load
        float w = expf(lrelu(g_as1[s * 2 + h] + adv) - m);
        ssum += w;
        float4 hv = *(const float4*)(hb + (size_t)s * 256);
        ax = fmaf(w, hv.x, ax); ay = fmaf(w, hv.y, ay);
        az = fmaf(w, hv.z, az); aw = fmaf(w, hv.w, aw);
    }
    float inv = 1.f / (ssum + 1e-16f);
    int col = h * 128 + lane * 4;
    float4 o;
    o.x = eluf(ax * inv + g1_b[col + 0]);
    o.y = eluf(ay * inv + g1_b[col + 1]);
    o.z = eluf(az * inv + g1_b[col + 2]);
    o.w = eluf(aw * inv + g1_b[col + 3]);
    *(float4*)(g_x1 + (size_t)node * 256 + col) = o;
}

// ---------------- GAT2 projection + attention coefficients --------------------
// h2[n,:] = x1[n,:] @ g2_W (256x4); as2/ad2 dot with g2_as/g2_ad. Warp per node.
__global__ __launch_bounds__(256) void h2_kernel(
    const float* __restrict__ g2_W, const float* __restrict__ g2_as,
    const float* __restrict__ g2_ad, int n)
{
    __shared__ float4 sW[256];
    __shared__ float4 s_as, s_ad;
    const int tid = threadIdx.x;
    sW[tid] = *(const float4*)(g2_W + tid * 4);
    if (tid == 0) { s_as = *(const float4*)g2_as; s_ad = *(const float4*)g2_ad; }
    __syncthreads();
    int node = blockIdx.x * 8 + (tid >> 5);
    int lane = tid & 31;
    if (node >= n) return;
    float a0 = 0.f, a1 = 0.f, a2 = 0.f, a3 = 0.f;
    const float* xr = g_x1 + (size_t)node * 256;
    for (int k = lane; k < 256; k += 32) {
        float x = xr[k];
        float4 w = sW[k];
        a0 = fmaf(x, w.x, a0); a1 = fmaf(x, w.y, a1);
        a2 = fmaf(x, w.z, a2); a3 = fmaf(x, w.w, a3);
    }
#pragma unroll
    for (int o = 16; o; o >>= 1) {
        a0 += __shfl_xor_sync(0xffffffffu, a0, o);
        a1 += __shfl_xor_sync(0xffffffffu, a1, o);
        a2 += __shfl_xor_sync(0xffffffffu, a2, o);
        a3 += __shfl_xor_sync(0xffffffffu, a3, o);
    }
    if (lane == 0) {
        *(float4*)(g_h2 + (size_t)node * 4) = make_float4(a0, a1, a2, a3);
        g_as2[node] = a0 * s_as.x + a1 * s_as.y + a2 * s_as.z + a3 * s_as.w;
        g_ad2[node] = a0 * s_ad.x + a1 * s_ad.y + a2 * s_ad.z + a3 * s_ad.w;
    }
}

// ---------------- GAT2 aggregate -> final output ------------------------------
__global__ __launch_bounds__(256) void gat2_kernel(
    const float* __restrict__ g2_b, float* __restrict__ out, int n)
{
    int node = blockIdx.x * 8 + (threadIdx.x >> 5);
    int lane = threadIdx.x & 31;
    if (node >= n) return;
    int beg = g_rowptr[node], end = g_rowptr[node + 1];
    float adv = g_ad2[node];

    float m = -1e30f;
    for (int i = beg + lane; i < end; i += 32) {
        int s = g_csr[i];
        m = fmaxf(m, lrelu(g_as2[s] + adv));
    }
#pragma unroll
    for (int o = 16; o; o >>= 1) m = fmaxf(m, __shfl_xor_sync(0xffffffffu, m, o));

    float ssum = 0.f, a0 = 0.f, a1 = 0.f, a2 = 0.f, a3 = 0.f;
    for (int i = beg + lane; i < end; i += 32) {
        int s = g_csr[i];
        float w = expf(lrelu(g_as2[s] + adv) - m);
        ssum += w;
        float4 hv = *(const float4*)(g_h2 + (size_t)s * 4);
        a0 = fmaf(w, hv.x, a0); a1 = fmaf(w, hv.y, a1);
        a2 = fmaf(w, hv.z, a2); a3 = fmaf(w, hv.w, a3);
    }
#pragma unroll
    for (int o = 16; o; o >>= 1) {
        ssum += __shfl_xor_sync(0xffffffffu, ssum, o);
        a0 += __shfl_xor_sync(0xffffffffu, a0, o);
        a1 += __shfl_xor_sync(0xffffffffu, a1, o);
        a2 += __shfl_xor_sync(0xffffffffu, a2, o);
        a3 += __shfl_xor_sync(0xffffffffu, a3, o);
    }
    if (lane == 0) {
        float inv = 1.f / (ssum + 1e-16f);
        float4 o4 = make_float4(a0 * inv + g2_b[0], a1 * inv + g2_b[1],
                                a2 * inv + g2_b[2], a3 * inv + g2_b[3]);
        *(float4*)(out + (size_t)node * 4) = o4;
    }
}

// ---------------- launch -------------------------------------------------------
extern "C" void kernel_launch(void* const* d_in, const int* in_sizes, int n_in,
                              void* d_out, int out_size)
{
    (void)n_in; (void)out_size;
    const float* text     = (const float*)d_in[0];
    const float* mel      = (const float*)d_in[1];
    const int*   ei       = (const int*)  d_in[2];
    const float* mel_W    = (const float*)d_in[3];
    const float* mel_b    = (const float*)d_in[4];
    const float* concat_W = (const float*)d_in[5];
    const float* concat_b = (const float*)d_in[6];
    const float* g1_W     = (const float*)d_in[7];
    const float* g1_as    = (const float*)d_in[8];
    const float* g1_ad    = (const float*)d_in[9];
    const float* g1_b     = (const float*)d_in[10];
    const float* g2_W     = (const float*)d_in[11];
    const float* g2_as    = (const float*)d_in[12];
    const float* g2_ad    = (const float*)d_in[13];
    const float* g2_b     = (const float*)d_in[14];
    float* out = (float*)d_out;

    const int n    = in_sizes[0] / TXT;       // 20000
    const int E    = in_sizes[2] / 2;         // 640000
    const int Etot = E + n;                   // 660000

    float *p_melf, *p_x0, *p_h1;
    cudaGetSymbolAddress((void**)&p_melf, g_melf);
    cudaGetSymbolAddress((void**)&p_x0,   g_x0);
    cudaGetSymbolAddress((void**)&p_h1,   g_h1);

    const int mblocks = (n + BM - 1) / BM;    // 313

    // CSR build (independent of GEMMs; same stream -> sequential)
    init_deg_kernel<<<(n + 255) / 256, 256>>>(n);
    hist_kernel<<<(Etot + 255) / 256, 256>>>(ei, E, Etot);
    scan_kernel<<<1, 1024>>>(n);
    scatter_kernel<<<(Etot + 255) / 256, 256>>>(ei, E, Etot);

    // mel_feat = relu(mel @ mel_W + mel_b)
    gemm_kernel<<<dim3(mblocks, 1), 256>>>(mel, MELK, MELK, mel, MELK,
                                           mel_W, HID, mel_b,
                                           p_melf, HID, n, MELK, 1);
    // x0 = elu([text | mel_feat] @ concat_W + concat_b)
    gemm_kernel<<<dim3(mblocks, 1), 256>>>(text, TXT, TXT, p_melf, HID,
                                           concat_W, HID, concat_b,
                                           p_x0, HID, n, TXT + HID, 2);
    // h1 = x0 @ g1_W  (no bias, no act)
    gemm_kernel<<<dim3(mblocks, 2), 256>>>(p_x0, HID, HID, p_x0, HID,
                                           g1_W, 256, nullptr,
                                           p_h1, 256, n, HID, 0);

    att1_kernel<<<(2 * n + 7) / 8, 256>>>(g1_as, g1_ad, n);
    gat1_kernel<<<(2 * n + 7) / 8, 256>>>(g1_b, n);
    h2_kernel<<<(n + 7) / 8, 256>>>(g2_W, g2_as, g2_ad, n);
    gat2_kernel<<<(n + 7) / 8, 256>>>(g2_b, out, n);
}